// round 1
// baseline (speedup 1.0000x reference)
#include <cuda_runtime.h>
#include <math.h>

// LinearTimeMMDLoss:
//   pairs i in [0, m/2): xo=source[2i], xe=source[2i+1], yo=target[2i], ye=target[2i+1]
//   dxx=|xo-xe|^2, dyy=|yo-ye|^2, dxy=|xo-ye|^2, dyx=|xe-yo|^2   (over d=512)
//   bw = (dxx+dyy+dxy+dyx)/4 / 2^(5/2=2)
//   h_i = sum_{k=0..4} [exp(-dxx/b_k)+exp(-dyy/b_k)-exp(-dxy/b_k)-exp(-dyx/b_k)],
//         b_k = bw*2^k + 1e-6
//   out = mean_i h_i

#define D 512
#define D4 (D / 4)              // 128 float4 per row
#define WARPS_PER_BLOCK 8
#define THREADS (WARPS_PER_BLOCK * 32)
#define MAX_BLOCKS 8192

__device__ double g_block_partials[MAX_BLOCKS];

__global__ void mmd_pair_kernel(const float* __restrict__ source,
                                const float* __restrict__ target,
                                int m2)
{
    const int warp_id = threadIdx.x >> 5;
    const int lane    = threadIdx.x & 31;
    const int pair    = blockIdx.x * WARPS_PER_BLOCK + warp_id;

    double h = 0.0;

    if (pair < m2) {
        const float4* xo = (const float4*)(source + (size_t)(2 * pair)     * D);
        const float4* xe = (const float4*)(source + (size_t)(2 * pair + 1) * D);
        const float4* yo = (const float4*)(target + (size_t)(2 * pair)     * D);
        const float4* ye = (const float4*)(target + (size_t)(2 * pair + 1) * D);

        float dxx = 0.f, dyy = 0.f, dxy = 0.f, dyx = 0.f;

        #pragma unroll
        for (int k = 0; k < D4 / 32; k++) {
            int j = lane + 32 * k;
            float4 a = xo[j];
            float4 b = xe[j];
            float4 c = yo[j];
            float4 e = ye[j];

            float t;
            t = a.x - b.x; dxx = fmaf(t, t, dxx);
            t = a.y - b.y; dxx = fmaf(t, t, dxx);
            t = a.z - b.z; dxx = fmaf(t, t, dxx);
            t = a.w - b.w; dxx = fmaf(t, t, dxx);

            t = c.x - e.x; dyy = fmaf(t, t, dyy);
            t = c.y - e.y; dyy = fmaf(t, t, dyy);
            t = c.z - e.z; dyy = fmaf(t, t, dyy);
            t = c.w - e.w; dyy = fmaf(t, t, dyy);

            t = a.x - e.x; dxy = fmaf(t, t, dxy);
            t = a.y - e.y; dxy = fmaf(t, t, dxy);
            t = a.z - e.z; dxy = fmaf(t, t, dxy);
            t = a.w - e.w; dxy = fmaf(t, t, dxy);

            t = b.x - c.x; dyx = fmaf(t, t, dyx);
            t = b.y - c.y; dyx = fmaf(t, t, dyx);
            t = b.z - c.z; dyx = fmaf(t, t, dyx);
            t = b.w - c.w; dyx = fmaf(t, t, dyx);
        }

        // warp tree-reduce the four sums (deterministic)
        #pragma unroll
        for (int off = 16; off > 0; off >>= 1) {
            dxx += __shfl_xor_sync(0xffffffffu, dxx, off);
            dyy += __shfl_xor_sync(0xffffffffu, dyy, off);
            dxy += __shfl_xor_sync(0xffffffffu, dxy, off);
            dyx += __shfl_xor_sync(0xffffffffu, dyx, off);
        }

        if (lane == 0) {
            float bw = (dxx + dyy + dxy + dyx) * (0.25f * 0.25f); // /4 then /2^(5//2)=4
            float mult = 1.0f;
            #pragma unroll
            for (int k = 0; k < 5; k++) {
                float b  = bw * mult + 1e-6f;
                float ib = 1.0f / b;
                h += (double)expf(-dxx * ib) + (double)expf(-dyy * ib)
                   - (double)expf(-dxy * ib) - (double)expf(-dyx * ib);
                mult *= 2.0f;
            }
        }
    }

    // block reduce (lane 0 of each warp holds h)
    __shared__ double s_h[WARPS_PER_BLOCK];
    if (lane == 0) s_h[warp_id] = h;
    __syncthreads();
    if (threadIdx.x == 0) {
        double sum = 0.0;
        #pragma unroll
        for (int w = 0; w < WARPS_PER_BLOCK; w++) sum += s_h[w];
        g_block_partials[blockIdx.x] = sum;
    }
}

__global__ void mmd_final_reduce(float* __restrict__ out, int num_blocks, int m2)
{
    __shared__ double s[1024];
    double v = 0.0;
    for (int i = threadIdx.x; i < num_blocks; i += 1024)
        v += g_block_partials[i];
    s[threadIdx.x] = v;
    __syncthreads();
    #pragma unroll
    for (int off = 512; off > 0; off >>= 1) {
        if (threadIdx.x < off) s[threadIdx.x] += s[threadIdx.x + off];
        __syncthreads();
    }
    if (threadIdx.x == 0)
        out[0] = (float)(s[0] / (double)m2);
}

extern "C" void kernel_launch(void* const* d_in, const int* in_sizes, int n_in,
                              void* d_out, int out_size)
{
    const float* source = (const float*)d_in[0];
    const float* target = (const float*)d_in[1];
    float* out = (float*)d_out;

    const int m  = in_sizes[0] / D;   // 65536
    const int m2 = m / 2;             // 32768

    int blocks = (m2 + WARPS_PER_BLOCK - 1) / WARPS_PER_BLOCK;  // 4096
    if (blocks > MAX_BLOCKS) blocks = MAX_BLOCKS;

    mmd_pair_kernel<<<blocks, THREADS>>>(source, target, m2);
    mmd_final_reduce<<<1, 1024>>>(out, blocks, m2);
}